// round 14
// baseline (speedup 1.0000x reference)
#include <cuda_runtime.h>
#include <cuda_fp16.h>
#include <cstdint>
#include <cstring>

// score[e] = dot(h[src[e]], h[dst[e]]), D = 128.
// Pass 1: convert fp32 node table -> fp16 scratch (halves gather traffic).
// Pass 2: persistent grid-stride gather with software-pipelined index
// prefetch. 8 lanes/edge, 4 edges/group, HMUL2+fp32 dot, packed butterfly.

static constexpr int MAX_NODES = 100000;
static constexpr int D_FEAT = 128;
static constexpr int ROW_BYTES = D_FEAT * 2;        // 256B per fp16 row
static constexpr int LANES_PER_EDGE = 8;
static constexpr int CHUNK_BYTES = 32;              // 16 halves per lane

__device__ __align__(256) static __half g_h16[MAX_NODES * D_FEAT];  // 25.6 MB scratch

__device__ __forceinline__ unsigned h2_as_u32(__half2 h) {
    unsigned u; memcpy(&u, &h, 4); return u;
}
__device__ __forceinline__ __half2 u32_as_h2(unsigned u) {
    __half2 h; memcpy(&h, &u, 4); return h;
}

// ---------------- Pass 1: fp32 -> fp16 conversion --------------------------
__global__ void __launch_bounds__(256)
convert_kernel(const float4* __restrict__ h4, int n_chunks)  // n_chunks = floats/16
{
    int i = blockIdx.x * blockDim.x + threadIdx.x;
    if (i >= n_chunks) return;
    float4 x0 = h4[4 * i + 0];
    float4 x1 = h4[4 * i + 1];
    float4 x2 = h4[4 * i + 2];
    float4 x3 = h4[4 * i + 3];
    unsigned p0 = h2_as_u32(__floats2half2_rn(x0.x, x0.y));
    unsigned p1 = h2_as_u32(__floats2half2_rn(x0.z, x0.w));
    unsigned p2 = h2_as_u32(__floats2half2_rn(x1.x, x1.y));
    unsigned p3 = h2_as_u32(__floats2half2_rn(x1.z, x1.w));
    unsigned p4 = h2_as_u32(__floats2half2_rn(x2.x, x2.y));
    unsigned p5 = h2_as_u32(__floats2half2_rn(x2.z, x2.w));
    unsigned p6 = h2_as_u32(__floats2half2_rn(x3.x, x3.y));
    unsigned p7 = h2_as_u32(__floats2half2_rn(x3.z, x3.w));
    char* dst = reinterpret_cast<char*>(g_h16) + (size_t)i * 32;
    asm volatile("st.global.v8.b32 [%0], {%1,%2,%3,%4,%5,%6,%7,%8};"
                 :: "l"(dst), "r"(p0), "r"(p1), "r"(p2), "r"(p3),
                    "r"(p4), "r"(p5), "r"(p6), "r"(p7) : "memory");
}

// ---------------- Pass 2: edge dot on fp16 table ---------------------------
struct U8 { unsigned v[8]; };

__device__ __forceinline__ U8 ldg256(const void* p) {
    U8 u;
    asm volatile("ld.global.v8.b32 {%0,%1,%2,%3,%4,%5,%6,%7}, [%8];"
                 : "=r"(u.v[0]), "=r"(u.v[1]), "=r"(u.v[2]), "=r"(u.v[3]),
                   "=r"(u.v[4]), "=r"(u.v[5]), "=r"(u.v[6]), "=r"(u.v[7])
                 : "l"(p));
    return u;
}

__device__ __forceinline__ float dot16(const U8& a, const U8& b) {
    float s0 = 0.0f, s1 = 0.0f;
    #pragma unroll
    for (int j = 0; j < 8; j++) {
        __half2 p = __hmul2(u32_as_h2(a.v[j]), u32_as_h2(b.v[j]));
        float2 f = __half22float2(p);
        s0 += f.x;
        s1 += f.y;
    }
    return s0 + s1;
}

__device__ __forceinline__ void load_idx(const int* __restrict__ src,
                                         const int* __restrict__ dst,
                                         int g, int n_edges,
                                         int4& s, int4& d)
{
    const int e0 = g * 4;
    if (e0 + 3 < n_edges) {
        s = reinterpret_cast<const int4*>(src)[g];
        d = reinterpret_cast<const int4*>(dst)[g];
    } else {
        int last = n_edges - 1;
        s.x = src[e0];
        s.y = src[min(e0 + 1, last)];
        s.z = src[min(e0 + 2, last)];
        s.w = src[min(e0 + 3, last)];
        d.x = dst[e0];
        d.y = dst[min(e0 + 1, last)];
        d.z = dst[min(e0 + 2, last)];
        d.w = dst[min(e0 + 3, last)];
    }
}

__global__ void __launch_bounds__(256, 8)   // cap 32 regs -> 64 warps/SM
edge_dot_kernel(const int* __restrict__ src,
                const int* __restrict__ dst,
                float*     __restrict__ out,
                int n_edges, int n_groups)
{
    const int sub    = threadIdx.x & 7;
    const int stride = (gridDim.x * blockDim.x) >> 3;   // groups per sweep
    int g = (blockIdx.x * blockDim.x + threadIdx.x) >> 3;

    const char* base = reinterpret_cast<const char*>(g_h16);
    const unsigned off = (unsigned)sub * CHUNK_BYTES;

    int4 s, d;
    if (g < n_groups) load_idx(src, dst, g, n_edges, s, d);

    while (g < n_groups) {
        const int gn = g + stride;

        // Gathers for the current group: 8 independent LDG.256.
        U8 a0 = ldg256(base + (unsigned)s.x * ROW_BYTES + off);
        U8 b0 = ldg256(base + (unsigned)d.x * ROW_BYTES + off);
        U8 a1 = ldg256(base + (unsigned)s.y * ROW_BYTES + off);
        U8 b1 = ldg256(base + (unsigned)d.y * ROW_BYTES + off);
        U8 a2 = ldg256(base + (unsigned)s.z * ROW_BYTES + off);
        U8 b2 = ldg256(base + (unsigned)d.z * ROW_BYTES + off);
        U8 a3 = ldg256(base + (unsigned)s.w * ROW_BYTES + off);
        U8 b3 = ldg256(base + (unsigned)d.w * ROW_BYTES + off);

        // Prefetch next iteration's indices while gathers are in flight.
        int4 sn, dn;
        if (gn < n_groups) load_idx(src, dst, gn, n_edges, sn, dn);

        float sum0 = dot16(a0, b0);
        float sum1 = dot16(a1, b1);
        float sum2 = dot16(a2, b2);
        float sum3 = dot16(a3, b3);

        // Packed multi-value butterfly across the 8-lane group.
        float ra = sum0 + __shfl_xor_sync(0xFFFFFFFFu, sum0, 4);
        float rb = sum1 + __shfl_xor_sync(0xFFFFFFFFu, sum1, 4);
        float rc = sum2 + __shfl_xor_sync(0xFFFFFFFFu, sum2, 4);
        float rd = sum3 + __shfl_xor_sync(0xFFFFFFFFu, sum3, 4);
        const bool hi = (sub & 4) != 0;
        float x = hi ? rc : ra;
        float y = hi ? rd : rb;
        x += __shfl_xor_sync(0xFFFFFFFFu, x, 2);
        y += __shfl_xor_sync(0xFFFFFFFFu, y, 2);
        x += __shfl_xor_sync(0xFFFFFFFFu, x, 1);
        y += __shfl_xor_sync(0xFFFFFFFFu, y, 1);

        const int e0 = g * 4;
        if (sub == 0) {
            if (e0 + 1 < n_edges) {
                *reinterpret_cast<float2*>(out + e0) = make_float2(x, y);
            } else {
                out[e0] = x;
            }
        } else if (sub == 4 && e0 + 2 < n_edges) {
            if (e0 + 3 < n_edges) {
                *reinterpret_cast<float2*>(out + e0 + 2) = make_float2(x, y);
            } else {
                out[e0 + 2] = x;
            }
        }

        s = sn; d = dn; g = gn;
    }
}

extern "C" void kernel_launch(void* const* d_in, const int* in_sizes, int n_in,
                              void* d_out, int out_size)
{
    const float4* h4  = (const float4*)d_in[0];   // h: [N_NODES, 128] fp32
    const int*    src = (const int*)d_in[1];      // [E] int32
    const int*    dst = (const int*)d_in[2];      // [E] int32
    float*        out = (float*)d_out;            // [E] fp32

    const int n_feat_elems = in_sizes[0];          // N_NODES * 128
    const int n_edges      = in_sizes[1];

    // Pass 1: convert table to fp16 (each thread: 16 floats).
    const int n_chunks = n_feat_elems / 16;
    convert_kernel<<<(n_chunks + 255) / 256, 256>>>(h4, n_chunks);

    // Pass 2: persistent gather, 8 blocks/SM on 148 SMs.
    const int n_groups = (n_edges + 3) / 4;
    const int threads = 256;
    const int blocks = 148 * 8;
    edge_dot_kernel<<<blocks, threads>>>(src, dst, out, n_edges, n_groups);
}

// round 15
// speedup vs baseline: 3.9799x; 3.9799x over previous
#include <cuda_runtime.h>
#include <cuda_fp16.h>
#include <cstdint>
#include <cstring>

// score[e] = dot(h[src[e]], h[dst[e]]), D = 128.
// Pass 1: convert fp32 node table -> fp16 scratch (halves gather traffic).
// Pass 2: gather fp16 rows (256B) via ld.global.nc.v8.b32; dot = HMUL2 +
// dual fp32 accumulators. 8 lanes/edge, 4 edges/group, 8 blocks/SM.
// Packed multi-value butterfly reduction, float2 stores.

static constexpr int MAX_NODES = 100000;
static constexpr int D_FEAT = 128;
static constexpr int ROW_BYTES = D_FEAT * 2;        // 256B per fp16 row
static constexpr int LANES_PER_EDGE = 8;
static constexpr int CHUNK_BYTES = 32;              // 16 halves per lane

__device__ __align__(256) static __half g_h16[MAX_NODES * D_FEAT];  // 25.6 MB scratch

__device__ __forceinline__ unsigned h2_as_u32(__half2 h) {
    unsigned u; memcpy(&u, &h, 4); return u;
}
__device__ __forceinline__ __half2 u32_as_h2(unsigned u) {
    __half2 h; memcpy(&h, &u, 4); return h;
}

// ---------------- Pass 1: fp32 -> fp16 conversion --------------------------
__global__ void __launch_bounds__(256)
convert_kernel(const float4* __restrict__ h4, int n_chunks)  // n_chunks = floats/16
{
    int i = blockIdx.x * blockDim.x + threadIdx.x;
    if (i >= n_chunks) return;
    float4 x0 = h4[4 * i + 0];
    float4 x1 = h4[4 * i + 1];
    float4 x2 = h4[4 * i + 2];
    float4 x3 = h4[4 * i + 3];
    unsigned p0 = h2_as_u32(__floats2half2_rn(x0.x, x0.y));
    unsigned p1 = h2_as_u32(__floats2half2_rn(x0.z, x0.w));
    unsigned p2 = h2_as_u32(__floats2half2_rn(x1.x, x1.y));
    unsigned p3 = h2_as_u32(__floats2half2_rn(x1.z, x1.w));
    unsigned p4 = h2_as_u32(__floats2half2_rn(x2.x, x2.y));
    unsigned p5 = h2_as_u32(__floats2half2_rn(x2.z, x2.w));
    unsigned p6 = h2_as_u32(__floats2half2_rn(x3.x, x3.y));
    unsigned p7 = h2_as_u32(__floats2half2_rn(x3.z, x3.w));
    char* dst = reinterpret_cast<char*>(g_h16) + (size_t)i * 32;
    asm volatile("st.global.v8.b32 [%0], {%1,%2,%3,%4,%5,%6,%7,%8};"
                 :: "l"(dst), "r"(p0), "r"(p1), "r"(p2), "r"(p3),
                    "r"(p4), "r"(p5), "r"(p6), "r"(p7) : "memory");
}

// ---------------- Pass 2: edge dot on fp16 table ---------------------------
struct U8 { unsigned v[8]; };

__device__ __forceinline__ U8 ldg256nc(const void* p) {
    U8 u;
    asm volatile("ld.global.nc.v8.b32 {%0,%1,%2,%3,%4,%5,%6,%7}, [%8];"
                 : "=r"(u.v[0]), "=r"(u.v[1]), "=r"(u.v[2]), "=r"(u.v[3]),
                   "=r"(u.v[4]), "=r"(u.v[5]), "=r"(u.v[6]), "=r"(u.v[7])
                 : "l"(p));
    return u;
}

// 16-halves dot: HMUL2 per pair (frees both load regs in 1 instr), then
// cvt + dual fp32 accumulators.
__device__ __forceinline__ float dot16(const U8& a, const U8& b) {
    float s0 = 0.0f, s1 = 0.0f;
    #pragma unroll
    for (int j = 0; j < 8; j++) {
        __half2 p = __hmul2(u32_as_h2(a.v[j]), u32_as_h2(b.v[j]));
        float2 f = __half22float2(p);
        s0 += f.x;
        s1 += f.y;
    }
    return s0 + s1;
}

__global__ void __launch_bounds__(256, 8)   // cap 32 regs -> 64 warps/SM
edge_dot_kernel(const int* __restrict__ src,
                const int* __restrict__ dst,
                float*     __restrict__ out,
                int n_edges)
{
    const int gtid  = blockIdx.x * blockDim.x + threadIdx.x;
    const int group = gtid >> 3;            // 8 lanes per group, 4 edges each
    const int sub   = gtid & 7;

    const int e0 = group * 4;
    if (e0 >= n_edges) return;

    int4 s, d;
    if (e0 + 3 < n_edges) {
        s = reinterpret_cast<const int4*>(src)[group];
        d = reinterpret_cast<const int4*>(dst)[group];
    } else {
        int last = n_edges - 1;
        s.x = src[e0];
        s.y = src[min(e0 + 1, last)];
        s.z = src[min(e0 + 2, last)];
        s.w = src[min(e0 + 3, last)];
        d.x = dst[e0];
        d.y = dst[min(e0 + 1, last)];
        d.z = dst[min(e0 + 2, last)];
        d.w = dst[min(e0 + 3, last)];
    }

    const char* base = reinterpret_cast<const char*>(g_h16);
    const unsigned off = (unsigned)sub * CHUNK_BYTES;

    U8 a0 = ldg256nc(base + (unsigned)s.x * ROW_BYTES + off);
    U8 b0 = ldg256nc(base + (unsigned)d.x * ROW_BYTES + off);
    U8 a1 = ldg256nc(base + (unsigned)s.y * ROW_BYTES + off);
    U8 b1 = ldg256nc(base + (unsigned)d.y * ROW_BYTES + off);
    U8 a2 = ldg256nc(base + (unsigned)s.z * ROW_BYTES + off);
    U8 b2 = ldg256nc(base + (unsigned)d.z * ROW_BYTES + off);
    U8 a3 = ldg256nc(base + (unsigned)s.w * ROW_BYTES + off);
    U8 b3 = ldg256nc(base + (unsigned)d.w * ROW_BYTES + off);

    float sum0 = dot16(a0, b0);
    float sum1 = dot16(a1, b1);
    float sum2 = dot16(a2, b2);
    float sum3 = dot16(a3, b3);

    // Packed multi-value butterfly: off=4 step on all four sums, then the
    // low half of the group carries (e0,e1) and the high half (e2,e3).
    float ra = sum0 + __shfl_xor_sync(0xFFFFFFFFu, sum0, 4);
    float rb = sum1 + __shfl_xor_sync(0xFFFFFFFFu, sum1, 4);
    float rc = sum2 + __shfl_xor_sync(0xFFFFFFFFu, sum2, 4);
    float rd = sum3 + __shfl_xor_sync(0xFFFFFFFFu, sum3, 4);
    const bool hi = (sub & 4) != 0;
    float x = hi ? rc : ra;
    float y = hi ? rd : rb;
    x += __shfl_xor_sync(0xFFFFFFFFu, x, 2);
    y += __shfl_xor_sync(0xFFFFFFFFu, y, 2);
    x += __shfl_xor_sync(0xFFFFFFFFu, x, 1);
    y += __shfl_xor_sync(0xFFFFFFFFu, y, 1);

    if (sub == 0) {
        if (e0 + 1 < n_edges) {
            *reinterpret_cast<float2*>(out + e0) = make_float2(x, y);
        } else {
            out[e0] = x;
        }
    } else if (sub == 4 && e0 + 2 < n_edges) {
        if (e0 + 3 < n_edges) {
            *reinterpret_cast<float2*>(out + e0 + 2) = make_float2(x, y);
        } else {
            out[e0 + 2] = x;
        }
    }
}

extern "C" void kernel_launch(void* const* d_in, const int* in_sizes, int n_in,
                              void* d_out, int out_size)
{
    const float4* h4  = (const float4*)d_in[0];   // h: [N_NODES, 128] fp32
    const int*    src = (const int*)d_in[1];      // [E] int32
    const int*    dst = (const int*)d_in[2];      // [E] int32
    float*        out = (float*)d_out;            // [E] fp32

    const int n_feat_elems = in_sizes[0];          // N_NODES * 128
    const int n_edges      = in_sizes[1];

    // Pass 1: convert table to fp16 (each thread: 16 floats).
    const int n_chunks = n_feat_elems / 16;
    convert_kernel<<<(n_chunks + 255) / 256, 256>>>(h4, n_chunks);

    // Pass 2: edge dots.
    const int threads = 256;
    const int edges_per_block = (threads / LANES_PER_EDGE) * 4;  // 128
    const int blocks = (n_edges + edges_per_block - 1) / edges_per_block;
    edge_dot_kernel<<<blocks, threads>>>(src, dst, out, n_edges);
}